// round 16
// baseline (speedup 1.0000x reference)
#include <cuda_runtime.h>
#include <cuda_bf16.h>
#include <cstdint>

// ---------------- Problem constants ----------------
#define BATCH   65536
#define OUT_DIM 768
#define E_DIM   64
#define N_STAGES 4
#define N_CODES 256
#define BETA    0.25f

#define OFF_OUT  0
#define OFF_LOSS (BATCH * OUT_DIM)                 // 50331648
#define OFF_IDX  (BATCH * OUT_DIM + 1)             // 50331649

// ---------------- Scratch buffers (device globals; no cudaMalloc allowed) ----
__device__ float g_bufA[BATCH * 512];   // 512-wide fp32 activations
__device__ float g_bufB[BATCH * 256];
__device__ float g_bufC[BATCH * 128];
__device__ float g_z  [BATCH * 64];     // encoder output z
__device__ float g_xq [BATCH * 64];     // quantized x_q
__device__ float g_loss[N_STAGES];

// ======================= PTX helpers =======================
__device__ __forceinline__ uint32_t smem_u32(const void* p) {
    uint32_t a;
    asm("{ .reg .u64 t; cvta.to.shared.u64 t, %1; cvt.u32.u64 %0, t; }"
        : "=r"(a) : "l"(p));
    return a;
}

__device__ __forceinline__ void cp_async16(uint32_t dst, const void* src) {
    asm volatile("cp.async.cg.shared.global [%0], [%1], 16;"
                 :: "r"(dst), "l"(src) : "memory");
}
#define CP_COMMIT()  asm volatile("cp.async.commit_group;" ::: "memory")
#define CP_WAIT(n)   asm volatile("cp.async.wait_group %0;" :: "n"(n) : "memory")

__device__ __forceinline__ uint32_t f2tf32(float f) {
    uint32_t r; asm("cvt.rna.tf32.f32 %0, %1;" : "=r"(r) : "f"(f)); return r;
}

// mma.sync m16n8k8 row.col tf32 -> f32 accumulate
__device__ __forceinline__ void mma1688(float* c, const uint32_t* a, const uint32_t* b) {
    asm volatile(
        "mma.sync.aligned.m16n8k8.row.col.f32.tf32.tf32.f32 "
        "{%0,%1,%2,%3}, {%4,%5,%6,%7}, {%8,%9}, {%0,%1,%2,%3};"
        : "+f"(c[0]), "+f"(c[1]), "+f"(c[2]), "+f"(c[3])
        : "r"(a[0]), "r"(a[1]), "r"(a[2]), "r"(a[3]), "r"(b[0]), "r"(b[1]));
}

// Packed fp32x2 helpers (Blackwell). Each half rounds exactly like scalar FFMA.
__device__ __forceinline__ unsigned long long pack_f32x2(float lo, float hi) {
    unsigned long long r;
    asm("mov.b64 %0, {%1, %2};" : "=l"(r) : "f"(lo), "f"(hi));
    return r;
}
__device__ __forceinline__ void unpack_f32x2(float& lo, float& hi, unsigned long long v) {
    asm("mov.b64 {%0, %1}, %2;" : "=f"(lo), "=f"(hi) : "l"(v));
}
__device__ __forceinline__ void fma_f32x2(unsigned long long& c,
                                          unsigned long long a, unsigned long long b) {
    asm("fma.rn.f32x2 %0, %1, %2, %0;" : "+l"(c) : "l"(a), "l"(b));
}

#define TSTR 36
#define TF32_SMEM (2 * 2 * 128 * TSTR * 4)   // 73728 bytes

// ================= tf32 decoder GEMM (R11-proven, in-loop cvt) =================
template<bool RELU>
__global__ void __launch_bounds__(256) tf32_gemm(
    const float* __restrict__ A, const float* __restrict__ W,
    const float* __restrict__ bias, float* __restrict__ C, int N, int K)
{
    extern __shared__ float smf[];
    float* sA = smf;                       // [2][128*TSTR]
    float* sB = smf + 2 * 128 * TSTR;      // [2][128*TSTR]

    const int tid  = threadIdx.x;
    const int lane = tid & 31;
    const int wid  = tid >> 5;
    const int wm   = wid & 1;
    const int wn   = wid >> 1;
    const int row0 = blockIdx.y * 128;
    const int col0 = blockIdx.x * 128;
    const int wrow = wm * 64;
    const int wcol = wn * 32;
    const int g = lane >> 2;
    const int t = lane & 3;

    float acc[4][4][4];
#pragma unroll
    for (int i = 0; i < 4; i++)
#pragma unroll
        for (int j = 0; j < 4; j++)
#pragma unroll
            for (int k = 0; k < 4; k++) acc[i][j][k] = 0.f;

    auto load_tile = [&](int b, int k0) {
        float* da = sA + b * 128 * TSTR;
        float* db = sB + b * 128 * TSTR;
#pragma unroll
        for (int i = 0; i < 4; i++) {
            int idx = tid + i * 256;
            int r = idx >> 3, s = idx & 7;
            cp_async16(smem_u32(da + r * TSTR + s * 4),
                       A + (size_t)(row0 + r) * K + k0 + s * 4);
            cp_async16(smem_u32(db + r * TSTR + s * 4),
                       W + (size_t)(col0 + r) * K + k0 + s * 4);
        }
    };

    const int nk = K >> 5;
    load_tile(0, 0);
    CP_COMMIT();

    for (int tt = 0; tt < nk; tt++) {
        const int cur = tt & 1;
        if (tt + 1 < nk) { load_tile(cur ^ 1, (tt + 1) << 5); CP_COMMIT(); CP_WAIT(1); }
        else             { CP_WAIT(0); }
        __syncthreads();

        const float* pa = sA + cur * 128 * TSTR;
        const float* pb = sB + cur * 128 * TSTR;

#pragma unroll
        for (int kk = 0; kk < 4; kk++) {
            const int kb = kk * 8;
            uint32_t af[4][4], bf[4][2];
#pragma unroll
            for (int mt = 0; mt < 4; mt++) {
                const float* p = pa + (wrow + mt * 16 + g) * TSTR + kb + t;
                af[mt][0] = f2tf32(p[0]);
                af[mt][1] = f2tf32(p[8 * TSTR]);
                af[mt][2] = f2tf32(p[4]);
                af[mt][3] = f2tf32(p[8 * TSTR + 4]);
            }
#pragma unroll
            for (int nt = 0; nt < 4; nt++) {
                const float* p = pb + (wcol + nt * 8 + g) * TSTR + kb + t;
                bf[nt][0] = f2tf32(p[0]);
                bf[nt][1] = f2tf32(p[4]);
            }
#pragma unroll
            for (int mt = 0; mt < 4; mt++)
#pragma unroll
                for (int nt = 0; nt < 4; nt++)
                    mma1688(acc[mt][nt], af[mt], bf[nt]);
        }
        __syncthreads();
    }

#pragma unroll
    for (int mt = 0; mt < 4; mt++) {
        const int rlo = row0 + wrow + mt * 16 + g;
        const int rhi = rlo + 8;
#pragma unroll
        for (int nt = 0; nt < 4; nt++) {
            const int c = col0 + wcol + nt * 8 + t * 2;
            float v0 = acc[mt][nt][0] + bias[c];
            float v1 = acc[mt][nt][1] + bias[c + 1];
            float v2 = acc[mt][nt][2] + bias[c];
            float v3 = acc[mt][nt][3] + bias[c + 1];
            if (RELU) {
                v0 = fmaxf(v0, 0.f); v1 = fmaxf(v1, 0.f);
                v2 = fmaxf(v2, 0.f); v3 = fmaxf(v3, 0.f);
            }
            *reinterpret_cast<float2*>(C + (size_t)rlo * N + c) = make_float2(v0, v1);
            *reinterpret_cast<float2*>(C + (size_t)rhi * N + c) = make_float2(v2, v3);
        }
    }
}

// ---------------- Encoder GEMM (fp32, f32x2 packed FMA, BK=8, double-buffered) -
// Numerics: fma.rn.f32x2 rounds each half exactly like scalar FFMA, and each
// acc element keeps its original accumulation order -> z is bit-identical to
// the scalar-FFMA version (indices preserved exactly).
template<int BM, int BN, int BK, int TM, int TN, bool RELU>
__global__ void __launch_bounds__(256, 2) gemm_kernel(
    const float* __restrict__ A, const float* __restrict__ W,
    const float* __restrict__ bias, float* __restrict__ C,
    int M, int N, int K)
{
    __shared__ __align__(16) float As[2][BK][BM];
    __shared__ __align__(16) float Bs[2][BK][BN];

    constexpr int NP = TN / 2;             // packed column pairs

    const int tid  = threadIdx.x;
    const int NTX  = BN / TN;
    const int tx   = tid % NTX;
    const int ty   = tid / NTX;
    const int row0 = blockIdx.y * BM;
    const int col0 = blockIdx.x * BN;

    unsigned long long acc2[TM][NP];
#pragma unroll
    for (int i = 0; i < TM; i++)
#pragma unroll
        for (int j = 0; j < NP; j++) acc2[i][j] = 0ull;   // {+0.f, +0.f}

    const int a_row = tid >> 1;
    const int a_col = (tid & 1) * 4;
    const float* Aptr = A + (row0 + a_row) * K + a_col;

    const bool b_active = (tid < (BN * BK) / 4);
    const int b_row = tid >> 1;
    const int b_col = (tid & 1) * 4;
    const float* Wptr = W + (col0 + b_row) * K + b_col;

    const int nk = K / BK;

    {
        float4 av = *reinterpret_cast<const float4*>(Aptr);
        float4 bv = make_float4(0.f, 0.f, 0.f, 0.f);
        if (b_active) bv = *reinterpret_cast<const float4*>(Wptr);
        As[0][a_col + 0][a_row] = av.x;
        As[0][a_col + 1][a_row] = av.y;
        As[0][a_col + 2][a_row] = av.z;
        As[0][a_col + 3][a_row] = av.w;
        if (b_active) {
            Bs[0][b_col + 0][b_row] = bv.x;
            Bs[0][b_col + 1][b_row] = bv.y;
            Bs[0][b_col + 2][b_row] = bv.z;
            Bs[0][b_col + 3][b_row] = bv.w;
        }
    }
    __syncthreads();

    for (int t = 0; t < nk; t++) {
        const int cur = t & 1;
        const int nxt = cur ^ 1;

        float4 av, bv;
        const bool have_next = (t + 1 < nk);
        if (have_next) {
            av = *reinterpret_cast<const float4*>(Aptr + (t + 1) * BK);
            if (b_active) bv = *reinterpret_cast<const float4*>(Wptr + (t + 1) * BK);
        }

#pragma unroll
        for (int kk = 0; kk < BK; kk++) {
            float a[TM], b[TN];
#pragma unroll
            for (int i = 0; i < TM; i += 4) {
                float4 v = *reinterpret_cast<const float4*>(&As[cur][kk][ty * TM + i]);
                a[i] = v.x; a[i + 1] = v.y; a[i + 2] = v.z; a[i + 3] = v.w;
            }
#pragma unroll
            for (int j = 0; j < TN; j += 4) {
                float4 v = *reinterpret_cast<const float4*>(&Bs[cur][kk][tx * TN + j]);
                b[j] = v.x; b[j + 1] = v.y; b[j + 2] = v.z; b[j + 3] = v.w;
            }
            unsigned long long b2[NP];
#pragma unroll
            for (int j = 0; j < NP; j++) b2[j] = pack_f32x2(b[2 * j], b[2 * j + 1]);
#pragma unroll
            for (int i = 0; i < TM; i++) {
                unsigned long long a2 = pack_f32x2(a[i], a[i]);
#pragma unroll
                for (int j = 0; j < NP; j++)
                    fma_f32x2(acc2[i][j], a2, b2[j]);
            }
        }

        if (have_next) {
            As[nxt][a_col + 0][a_row] = av.x;
            As[nxt][a_col + 1][a_row] = av.y;
            As[nxt][a_col + 2][a_row] = av.z;
            As[nxt][a_col + 3][a_row] = av.w;
            if (b_active) {
                Bs[nxt][b_col + 0][b_row] = bv.x;
                Bs[nxt][b_col + 1][b_row] = bv.y;
                Bs[nxt][b_col + 2][b_row] = bv.z;
                Bs[nxt][b_col + 3][b_row] = bv.w;
            }
        }
        __syncthreads();
    }

#pragma unroll
    for (int i = 0; i < TM; i++) {
        int r = row0 + ty * TM + i;
#pragma unroll
        for (int j = 0; j < TN; j += 4) {
            int c = col0 + tx * TN + j;
            float e0, e1, e2, e3;
            unpack_f32x2(e0, e1, acc2[i][(j >> 1) + 0]);
            unpack_f32x2(e2, e3, acc2[i][(j >> 1) + 1]);
            float4 v;
            v.x = e0 + bias[c + 0];
            v.y = e1 + bias[c + 1];
            v.z = e2 + bias[c + 2];
            v.w = e3 + bias[c + 3];
            if (RELU) {
                v.x = fmaxf(v.x, 0.f); v.y = fmaxf(v.y, 0.f);
                v.z = fmaxf(v.z, 0.f); v.w = fmaxf(v.w, 0.f);
            }
            *reinterpret_cast<float4*>(&C[r * N + c]) = v;
        }
    }
}

// ---------------- Residual quantization (R11-proven two-chunk version) --------
__global__ void __launch_bounds__(256) rq_kernel(
    const float* __restrict__ z, const float* __restrict__ cbg,
    float* __restrict__ xq_out, float* __restrict__ dout)
{
    __shared__ __align__(16) float rs[32 * 64];
    __shared__ float cbs[128 * 65];
    __shared__ float esq[128];
    __shared__ float lred[8 * 4];

    const int tid  = threadIdx.x;
    const int lane = tid & 31;
    const int wid  = tid >> 5;
    const int rowg = blockIdx.x * 32;
    const int myrow0 = wid * 4;

#pragma unroll
    for (int i = 0; i < 2; i++) {
        int idx4 = i * 256 + tid;
        *reinterpret_cast<float4*>(&rs[idx4 * 4]) =
            *reinterpret_cast<const float4*>(&z[rowg * 64 + idx4 * 4]);
    }

    float xq[4][2];
#pragma unroll
    for (int r = 0; r < 4; r++) { xq[r][0] = 0.f; xq[r][1] = 0.f; }
    float lacc[N_STAGES] = {0.f, 0.f, 0.f, 0.f};

    for (int s = 0; s < N_STAGES; s++) {
        float bd[4]; int bi[4];
#pragma unroll
        for (int r = 0; r < 4; r++) { bd[r] = 3.4e38f; bi[r] = 0x7fffffff; }

        for (int ch = 0; ch < 2; ch++) {
            __syncthreads();
            const float* src = cbg + (s * N_CODES + ch * 128) * 64;
#pragma unroll
            for (int i = 0; i < 8; i++) {
                int idx4 = i * 256 + tid;
                int c = idx4 >> 4;
                int k4 = idx4 & 15;
                float4 v = *reinterpret_cast<const float4*>(&src[idx4 * 4]);
                float* dst = &cbs[c * 65 + k4 * 4];
                dst[0] = v.x; dst[1] = v.y; dst[2] = v.z; dst[3] = v.w;
            }
            __syncthreads();
            if (tid < 128) {
                float ssum = 0.f;
#pragma unroll 16
                for (int k = 0; k < 64; k++) {
                    float e = cbs[tid * 65 + k];
                    ssum += e * e;
                }
                esq[tid] = ssum;
            }
            __syncthreads();

            float dot[4][4];
#pragma unroll
            for (int r = 0; r < 4; r++)
#pragma unroll
                for (int j = 0; j < 4; j++) dot[r][j] = 0.f;

#pragma unroll 16
            for (int k = 0; k < 64; k++) {
                float a0 = rs[(myrow0 + 0) * 64 + k];
                float a1 = rs[(myrow0 + 1) * 64 + k];
                float a2 = rs[(myrow0 + 2) * 64 + k];
                float a3 = rs[(myrow0 + 3) * 64 + k];
                float b0 = cbs[(lane     ) * 65 + k];
                float b1 = cbs[(lane + 32) * 65 + k];
                float b2 = cbs[(lane + 64) * 65 + k];
                float b3 = cbs[(lane + 96) * 65 + k];
                dot[0][0] += a0 * b0; dot[0][1] += a0 * b1; dot[0][2] += a0 * b2; dot[0][3] += a0 * b3;
                dot[1][0] += a1 * b0; dot[1][1] += a1 * b1; dot[1][2] += a1 * b2; dot[1][3] += a1 * b3;
                dot[2][0] += a2 * b0; dot[2][1] += a2 * b1; dot[2][2] += a2 * b2; dot[2][3] += a2 * b3;
                dot[3][0] += a3 * b0; dot[3][1] += a3 * b1; dot[3][2] += a3 * b2; dot[3][3] += a3 * b3;
            }

#pragma unroll
            for (int j = 0; j < 4; j++) {
                int c  = ch * 128 + lane + 32 * j;
                float ev = esq[lane + 32 * j];
#pragma unroll
                for (int r = 0; r < 4; r++) {
                    float d = ev - 2.f * dot[r][j];
                    if (d < bd[r] || (d == bd[r] && c < bi[r])) { bd[r] = d; bi[r] = c; }
                }
            }
        }

#pragma unroll
        for (int r = 0; r < 4; r++) {
            float d = bd[r]; int idx = bi[r];
#pragma unroll
            for (int off = 16; off; off >>= 1) {
                float od = __shfl_xor_sync(0xffffffffu, d, off);
                int   oi = __shfl_xor_sync(0xffffffffu, idx, off);
                if (od < d || (od == d && oi < idx)) { d = od; idx = oi; }
            }
            const float* qp = cbg + (s * N_CODES + idx) * 64;
            float q0 = qp[lane], q1 = qp[lane + 32];
            int base = (myrow0 + r) * 64;
            float r0 = rs[base + lane], r1 = rs[base + lane + 32];
            float d0 = q0 - r0, d1 = q1 - r1;
            lacc[s] += d0 * d0 + d1 * d1;
            xq[r][0] += q0; xq[r][1] += q1;
            rs[base + lane]      = r0 - q0;
            rs[base + lane + 32] = r1 - q1;
            if (lane == 0)
                dout[OFF_IDX + (rowg + myrow0 + r) * 4 + s] = (float)idx;
        }
        __syncwarp();
    }

#pragma unroll
    for (int r = 0; r < 4; r++) {
        int grow = rowg + myrow0 + r;
        xq_out[grow * 64 + lane]      = xq[r][0];
        xq_out[grow * 64 + lane + 32] = xq[r][1];
    }

#pragma unroll
    for (int s = 0; s < N_STAGES; s++) {
        float v = lacc[s];
#pragma unroll
        for (int off = 16; off; off >>= 1) v += __shfl_xor_sync(0xffffffffu, v, off);
        if (lane == 0) lred[wid * 4 + s] = v;
    }
    __syncthreads();
    if (tid < N_STAGES) {
        float sum = 0.f;
#pragma unroll
        for (int w = 0; w < 8; w++) sum += lred[w * 4 + tid];
        atomicAdd(&g_loss[tid], sum);
    }
}

__global__ void zero_loss_kernel() {
    if (threadIdx.x < N_STAGES) g_loss[threadIdx.x] = 0.f;
}

__global__ void finalize_loss_kernel(float* __restrict__ dout) {
    float total = g_loss[0] + g_loss[1] + g_loss[2] + g_loss[3];
    dout[OFF_LOSS] = (1.f + BETA) * total / (4.f * (float)BATCH * 64.f);
}

// ---------------- Launch ----------------
extern "C" void kernel_launch(void* const* d_in, const int* in_sizes, int n_in,
                              void* d_out, int out_size) {
    const float* x   = (const float*)d_in[0];
    const float* ew0 = (const float*)d_in[1];  const float* eb0 = (const float*)d_in[2];
    const float* ew1 = (const float*)d_in[3];  const float* eb1 = (const float*)d_in[4];
    const float* ew2 = (const float*)d_in[5];  const float* eb2 = (const float*)d_in[6];
    const float* ew3 = (const float*)d_in[7];  const float* eb3 = (const float*)d_in[8];
    const float* dw0 = (const float*)d_in[9];  const float* db0 = (const float*)d_in[10];
    const float* dw1 = (const float*)d_in[11]; const float* db1 = (const float*)d_in[12];
    const float* dw2 = (const float*)d_in[13]; const float* db2 = (const float*)d_in[14];
    const float* dw3 = (const float*)d_in[15]; const float* db3 = (const float*)d_in[16];
    const float* cb  = (const float*)d_in[17];
    float* out = (float*)d_out;

    float *bufA, *bufB, *bufC, *zb, *xqb;
    cudaGetSymbolAddress((void**)&bufA, g_bufA);
    cudaGetSymbolAddress((void**)&bufB, g_bufB);
    cudaGetSymbolAddress((void**)&bufC, g_bufC);
    cudaGetSymbolAddress((void**)&zb,   g_z);
    cudaGetSymbolAddress((void**)&xqb,  g_xq);

    cudaFuncSetAttribute(tf32_gemm<true >, cudaFuncAttributeMaxDynamicSharedMemorySize, TF32_SMEM);
    cudaFuncSetAttribute(tf32_gemm<false>, cudaFuncAttributeMaxDynamicSharedMemorySize, TF32_SMEM);

    dim3 blk(256);
    const int MT = BATCH / 128;   // 512 M-tiles

    // Encoder: 768 -> 512 -> 256 -> 128 -> 64 (fp32 via packed f32x2 FMA;
    // bit-identical z -> indices exact)
    gemm_kernel<128,128,8,8,8,true ><<<dim3(4, MT), blk>>>(x,    ew0, eb0, bufA, BATCH, 512, 768);
    gemm_kernel<128,128,8,8,8,true ><<<dim3(2, MT), blk>>>(bufA, ew1, eb1, bufB, BATCH, 256, 512);
    gemm_kernel<128,128,8,8,8,true ><<<dim3(1, MT), blk>>>(bufB, ew2, eb2, bufC, BATCH, 128, 256);
    gemm_kernel<128, 64,8,8,4,false><<<dim3(1, MT), blk>>>(bufC, ew3, eb3, zb,   BATCH,  64, 128);

    // Residual quantization (indices -> d_out, x_q fp32 -> xqb)
    zero_loss_kernel<<<1, 32>>>();
    rq_kernel<<<BATCH / 32, 256>>>(zb, cb, xqb, out);
    finalize_loss_kernel<<<1, 1>>>(out);

    // Decoder: tf32 mma.sync GEMMs (R11-proven, in-loop cvt).
    tf32_gemm<true ><<<dim3(1, MT), blk, TF32_SMEM>>>(xqb,  dw0, db0, bufC, 128,  64);
    tf32_gemm<true ><<<dim3(2, MT), blk, TF32_SMEM>>>(bufC, dw1, db1, bufB, 256, 128);
    tf32_gemm<true ><<<dim3(4, MT), blk, TF32_SMEM>>>(bufB, dw2, db2, bufA, 512, 256);
    tf32_gemm<false><<<dim3(6, MT), blk, TF32_SMEM>>>(bufA, dw3, db3, out,  768, 512);
}

// round 17
// speedup vs baseline: 1.0907x; 1.0907x over previous
#include <cuda_runtime.h>
#include <cuda_bf16.h>
#include <cstdint>

// ---------------- Problem constants ----------------
#define BATCH   65536
#define OUT_DIM 768
#define E_DIM   64
#define N_STAGES 4
#define N_CODES 256
#define BETA    0.25f

#define OFF_OUT  0
#define OFF_LOSS (BATCH * OUT_DIM)                 // 50331648
#define OFF_IDX  (BATCH * OUT_DIM + 1)             // 50331649

// ---------------- Scratch buffers (device globals; no cudaMalloc allowed) ----
__device__ float g_bufA[BATCH * 512];   // 512-wide fp32 activations
__device__ float g_bufB[BATCH * 256];
__device__ float g_bufC[BATCH * 128];
__device__ float g_z  [BATCH * 64];     // encoder output z
__device__ float g_xq [BATCH * 64];     // quantized x_q
__device__ float g_loss[N_STAGES];

// ======================= PTX helpers =======================
__device__ __forceinline__ uint32_t smem_u32(const void* p) {
    uint32_t a;
    asm("{ .reg .u64 t; cvta.to.shared.u64 t, %1; cvt.u32.u64 %0, t; }"
        : "=r"(a) : "l"(p));
    return a;
}

__device__ __forceinline__ void cp_async16(uint32_t dst, const void* src) {
    asm volatile("cp.async.cg.shared.global [%0], [%1], 16;"
                 :: "r"(dst), "l"(src) : "memory");
}
#define CP_COMMIT()  asm volatile("cp.async.commit_group;" ::: "memory")
#define CP_WAIT(n)   asm volatile("cp.async.wait_group %0;" :: "n"(n) : "memory")

__device__ __forceinline__ uint32_t f2tf32(float f) {
    uint32_t r; asm("cvt.rna.tf32.f32 %0, %1;" : "=r"(r) : "f"(f)); return r;
}

// mma.sync m16n8k8 row.col tf32 -> f32 accumulate
__device__ __forceinline__ void mma1688(float* c, const uint32_t* a, const uint32_t* b) {
    asm volatile(
        "mma.sync.aligned.m16n8k8.row.col.f32.tf32.tf32.f32 "
        "{%0,%1,%2,%3}, {%4,%5,%6,%7}, {%8,%9}, {%0,%1,%2,%3};"
        : "+f"(c[0]), "+f"(c[1]), "+f"(c[2]), "+f"(c[3])
        : "r"(a[0]), "r"(a[1]), "r"(a[2]), "r"(a[3]), "r"(b[0]), "r"(b[1]));
}

#define TSTR 36
#define TF32_SMEM (2 * 2 * 128 * TSTR * 4)   // 73728 bytes

// ================= tf32 decoder GEMM (R11-proven, in-loop cvt) =================
template<bool RELU>
__global__ void __launch_bounds__(256) tf32_gemm(
    const float* __restrict__ A, const float* __restrict__ W,
    const float* __restrict__ bias, float* __restrict__ C, int N, int K)
{
    extern __shared__ float smf[];
    float* sA = smf;                       // [2][128*TSTR]
    float* sB = smf + 2 * 128 * TSTR;      // [2][128*TSTR]

    const int tid  = threadIdx.x;
    const int lane = tid & 31;
    const int wid  = tid >> 5;
    const int wm   = wid & 1;
    const int wn   = wid >> 1;
    const int row0 = blockIdx.y * 128;
    const int col0 = blockIdx.x * 128;
    const int wrow = wm * 64;
    const int wcol = wn * 32;
    const int g = lane >> 2;
    const int t = lane & 3;

    float acc[4][4][4];
#pragma unroll
    for (int i = 0; i < 4; i++)
#pragma unroll
        for (int j = 0; j < 4; j++)
#pragma unroll
            for (int k = 0; k < 4; k++) acc[i][j][k] = 0.f;

    auto load_tile = [&](int b, int k0) {
        float* da = sA + b * 128 * TSTR;
        float* db = sB + b * 128 * TSTR;
#pragma unroll
        for (int i = 0; i < 4; i++) {
            int idx = tid + i * 256;
            int r = idx >> 3, s = idx & 7;
            cp_async16(smem_u32(da + r * TSTR + s * 4),
                       A + (size_t)(row0 + r) * K + k0 + s * 4);
            cp_async16(smem_u32(db + r * TSTR + s * 4),
                       W + (size_t)(col0 + r) * K + k0 + s * 4);
        }
    };

    const int nk = K >> 5;
    load_tile(0, 0);
    CP_COMMIT();

    for (int tt = 0; tt < nk; tt++) {
        const int cur = tt & 1;
        if (tt + 1 < nk) { load_tile(cur ^ 1, (tt + 1) << 5); CP_COMMIT(); CP_WAIT(1); }
        else             { CP_WAIT(0); }
        __syncthreads();

        const float* pa = sA + cur * 128 * TSTR;
        const float* pb = sB + cur * 128 * TSTR;

#pragma unroll
        for (int kk = 0; kk < 4; kk++) {
            const int kb = kk * 8;
            uint32_t af[4][4], bf[4][2];
#pragma unroll
            for (int mt = 0; mt < 4; mt++) {
                const float* p = pa + (wrow + mt * 16 + g) * TSTR + kb + t;
                af[mt][0] = f2tf32(p[0]);
                af[mt][1] = f2tf32(p[8 * TSTR]);
                af[mt][2] = f2tf32(p[4]);
                af[mt][3] = f2tf32(p[8 * TSTR + 4]);
            }
#pragma unroll
            for (int nt = 0; nt < 4; nt++) {
                const float* p = pb + (wcol + nt * 8 + g) * TSTR + kb + t;
                bf[nt][0] = f2tf32(p[0]);
                bf[nt][1] = f2tf32(p[4]);
            }
#pragma unroll
            for (int mt = 0; mt < 4; mt++)
#pragma unroll
                for (int nt = 0; nt < 4; nt++)
                    mma1688(acc[mt][nt], af[mt], bf[nt]);
        }
        __syncthreads();
    }

#pragma unroll
    for (int mt = 0; mt < 4; mt++) {
        const int rlo = row0 + wrow + mt * 16 + g;
        const int rhi = rlo + 8;
#pragma unroll
        for (int nt = 0; nt < 4; nt++) {
            const int c = col0 + wcol + nt * 8 + t * 2;
            float v0 = acc[mt][nt][0] + bias[c];
            float v1 = acc[mt][nt][1] + bias[c + 1];
            float v2 = acc[mt][nt][2] + bias[c];
            float v3 = acc[mt][nt][3] + bias[c + 1];
            if (RELU) {
                v0 = fmaxf(v0, 0.f); v1 = fmaxf(v1, 0.f);
                v2 = fmaxf(v2, 0.f); v3 = fmaxf(v3, 0.f);
            }
            *reinterpret_cast<float2*>(C + (size_t)rlo * N + c) = make_float2(v0, v1);
            *reinterpret_cast<float2*>(C + (size_t)rhi * N + c) = make_float2(v2, v3);
        }
    }
}

// ---------------- Encoder GEMM (fp32 SIMT, BK=8, double-buffered; R11-proven) --
template<int BM, int BN, int BK, int TM, int TN, bool RELU>
__global__ void __launch_bounds__(256, 2) gemm_kernel(
    const float* __restrict__ A, const float* __restrict__ W,
    const float* __restrict__ bias, float* __restrict__ C,
    int M, int N, int K)
{
    __shared__ __align__(16) float As[2][BK][BM];
    __shared__ __align__(16) float Bs[2][BK][BN];

    const int tid  = threadIdx.x;
    const int NTX  = BN / TN;
    const int tx   = tid % NTX;
    const int ty   = tid / NTX;
    const int row0 = blockIdx.y * BM;
    const int col0 = blockIdx.x * BN;

    float acc[TM][TN];
#pragma unroll
    for (int i = 0; i < TM; i++)
#pragma unroll
        for (int j = 0; j < TN; j++) acc[i][j] = 0.f;

    const int a_row = tid >> 1;
    const int a_col = (tid & 1) * 4;
    const float* Aptr = A + (row0 + a_row) * K + a_col;

    const bool b_active = (tid < (BN * BK) / 4);
    const int b_row = tid >> 1;
    const int b_col = (tid & 1) * 4;
    const float* Wptr = W + (col0 + b_row) * K + b_col;

    const int nk = K / BK;

    {
        float4 av = *reinterpret_cast<const float4*>(Aptr);
        float4 bv = make_float4(0.f, 0.f, 0.f, 0.f);
        if (b_active) bv = *reinterpret_cast<const float4*>(Wptr);
        As[0][a_col + 0][a_row] = av.x;
        As[0][a_col + 1][a_row] = av.y;
        As[0][a_col + 2][a_row] = av.z;
        As[0][a_col + 3][a_row] = av.w;
        if (b_active) {
            Bs[0][b_col + 0][b_row] = bv.x;
            Bs[0][b_col + 1][b_row] = bv.y;
            Bs[0][b_col + 2][b_row] = bv.z;
            Bs[0][b_col + 3][b_row] = bv.w;
        }
    }
    __syncthreads();

    for (int t = 0; t < nk; t++) {
        const int cur = t & 1;
        const int nxt = cur ^ 1;

        float4 av, bv;
        const bool have_next = (t + 1 < nk);
        if (have_next) {
            av = *reinterpret_cast<const float4*>(Aptr + (t + 1) * BK);
            if (b_active) bv = *reinterpret_cast<const float4*>(Wptr + (t + 1) * BK);
        }

#pragma unroll
        for (int kk = 0; kk < BK; kk++) {
            float a[TM], b[TN];
#pragma unroll
            for (int i = 0; i < TM; i += 4) {
                float4 v = *reinterpret_cast<const float4*>(&As[cur][kk][ty * TM + i]);
                a[i] = v.x; a[i + 1] = v.y; a[i + 2] = v.z; a[i + 3] = v.w;
            }
#pragma unroll
            for (int j = 0; j < TN; j += 4) {
                float4 v = *reinterpret_cast<const float4*>(&Bs[cur][kk][tx * TN + j]);
                b[j] = v.x; b[j + 1] = v.y; b[j + 2] = v.z; b[j + 3] = v.w;
            }
#pragma unroll
            for (int i = 0; i < TM; i++)
#pragma unroll
                for (int j = 0; j < TN; j++)
                    acc[i][j] += a[i] * b[j];
        }

        if (have_next) {
            As[nxt][a_col + 0][a_row] = av.x;
            As[nxt][a_col + 1][a_row] = av.y;
            As[nxt][a_col + 2][a_row] = av.z;
            As[nxt][a_col + 3][a_row] = av.w;
            if (b_active) {
                Bs[nxt][b_col + 0][b_row] = bv.x;
                Bs[nxt][b_col + 1][b_row] = bv.y;
                Bs[nxt][b_col + 2][b_row] = bv.z;
                Bs[nxt][b_col + 3][b_row] = bv.w;
            }
        }
        __syncthreads();
    }

#pragma unroll
    for (int i = 0; i < TM; i++) {
        int r = row0 + ty * TM + i;
#pragma unroll
        for (int j = 0; j < TN; j += 4) {
            int c = col0 + tx * TN + j;
            float4 v;
            v.x = acc[i][j + 0] + bias[c + 0];
            v.y = acc[i][j + 1] + bias[c + 1];
            v.z = acc[i][j + 2] + bias[c + 2];
            v.w = acc[i][j + 3] + bias[c + 3];
            if (RELU) {
                v.x = fmaxf(v.x, 0.f); v.y = fmaxf(v.y, 0.f);
                v.z = fmaxf(v.z, 0.f); v.w = fmaxf(v.w, 0.f);
            }
            *reinterpret_cast<float4*>(&C[r * N + c]) = v;
        }
    }
}

// ---------------- Residual quantization (64 rows/block, 8 rows/warp) ----------
// Per-row math is bit-identical to the 32-row version: same dot accumulation
// order, same chunk/j argmin scan, same warp-shuffle reduction. Only the loss
// scalar's addition order changes (already order-free via atomics).
// Dynamic smem: rs[64*64] | cbs[128*65] | esq[128] | lred[32]
#define RQ_SMEM ((4096 + 128 * 65 + 128 + 32) * 4)   // 50304 bytes

__global__ void __launch_bounds__(256) rq_kernel(
    const float* __restrict__ z, const float* __restrict__ cbg,
    float* __restrict__ xq_out, float* __restrict__ dout)
{
    extern __shared__ float dyn[];
    float* rs   = dyn;                   // 64 x 64 residuals
    float* cbs  = dyn + 4096;            // 128 x 65 codebook chunk (padded)
    float* esq  = cbs + 128 * 65;        // |e|^2 per chunk code
    float* lred = esq + 128;             // per-warp loss partials

    const int tid  = threadIdx.x;
    const int lane = tid & 31;
    const int wid  = tid >> 5;           // warp w -> rows w*8 .. w*8+7
    const int rowg = blockIdx.x * 64;
    const int myrow0 = wid * 8;

    // Load 64 rows of z (vectorized, coalesced).
#pragma unroll
    for (int i = 0; i < 4; i++) {
        int idx4 = i * 256 + tid;        // 0..1023 float4s
        *reinterpret_cast<float4*>(&rs[idx4 * 4]) =
            *reinterpret_cast<const float4*>(&z[rowg * 64 + idx4 * 4]);
    }

    float xq[8][2];
#pragma unroll
    for (int r = 0; r < 8; r++) { xq[r][0] = 0.f; xq[r][1] = 0.f; }
    float lacc[N_STAGES] = {0.f, 0.f, 0.f, 0.f};

    for (int s = 0; s < N_STAGES; s++) {
        float bd[8]; int bi[8];
#pragma unroll
        for (int r = 0; r < 8; r++) { bd[r] = 3.4e38f; bi[r] = 0x7fffffff; }

        for (int ch = 0; ch < 2; ch++) {
            __syncthreads();   // previous readers of cbs done
            const float* src = cbg + (s * N_CODES + ch * 128) * 64;
#pragma unroll
            for (int i = 0; i < 8; i++) {
                int idx4 = i * 256 + tid;          // 0..2047 float4s
                int c = idx4 >> 4;
                int k4 = idx4 & 15;
                float4 v = *reinterpret_cast<const float4*>(&src[idx4 * 4]);
                float* dst = &cbs[c * 65 + k4 * 4];
                dst[0] = v.x; dst[1] = v.y; dst[2] = v.z; dst[3] = v.w;
            }
            __syncthreads();
            if (tid < 128) {
                float ssum = 0.f;
#pragma unroll 16
                for (int k = 0; k < 64; k++) {
                    float e = cbs[tid * 65 + k];
                    ssum += e * e;
                }
                esq[tid] = ssum;
            }
            __syncthreads();

            // Distance mini-GEMM: 8 rows x 4 codes per thread.
            float dot[8][4];
#pragma unroll
            for (int r = 0; r < 8; r++)
#pragma unroll
                for (int j = 0; j < 4; j++) dot[r][j] = 0.f;

#pragma unroll 8
            for (int k = 0; k < 64; k++) {
                float b0 = cbs[(lane     ) * 65 + k];
                float b1 = cbs[(lane + 32) * 65 + k];
                float b2 = cbs[(lane + 64) * 65 + k];
                float b3 = cbs[(lane + 96) * 65 + k];
#pragma unroll
                for (int r = 0; r < 8; r++) {
                    float a = rs[(myrow0 + r) * 64 + k];
                    dot[r][0] += a * b0;
                    dot[r][1] += a * b1;
                    dot[r][2] += a * b2;
                    dot[r][3] += a * b3;
                }
            }

#pragma unroll
            for (int j = 0; j < 4; j++) {
                int c  = ch * 128 + lane + 32 * j;
                float ev = esq[lane + 32 * j];
#pragma unroll
                for (int r = 0; r < 8; r++) {
                    float d = ev - 2.f * dot[r][j];
                    if (d < bd[r] || (d == bd[r] && c < bi[r])) { bd[r] = d; bi[r] = c; }
                }
            }
        }

        // Warp argmin per row + residual/x_q/loss update.
#pragma unroll
        for (int r = 0; r < 8; r++) {
            float d = bd[r]; int idx = bi[r];
#pragma unroll
            for (int off = 16; off; off >>= 1) {
                float od = __shfl_xor_sync(0xffffffffu, d, off);
                int   oi = __shfl_xor_sync(0xffffffffu, idx, off);
                if (od < d || (od == d && oi < idx)) { d = od; idx = oi; }
            }
            const float* qp = cbg + (s * N_CODES + idx) * 64;
            float q0 = qp[lane], q1 = qp[lane + 32];
            int base = (myrow0 + r) * 64;
            float r0 = rs[base + lane], r1 = rs[base + lane + 32];
            float d0 = q0 - r0, d1 = q1 - r1;
            lacc[s] += d0 * d0 + d1 * d1;
            xq[r][0] += q0; xq[r][1] += q1;
            rs[base + lane]      = r0 - q0;
            rs[base + lane + 32] = r1 - q1;
            if (lane == 0)
                dout[OFF_IDX + (rowg + myrow0 + r) * 4 + s] = (float)idx;
        }
        __syncwarp();
    }

    // Write x_q.
#pragma unroll
    for (int r = 0; r < 8; r++) {
        int grow = rowg + myrow0 + r;
        xq_out[grow * 64 + lane]      = xq[r][0];
        xq_out[grow * 64 + lane + 32] = xq[r][1];
    }

    // Loss reduction: warp -> smem -> atomic.
#pragma unroll
    for (int s = 0; s < N_STAGES; s++) {
        float v = lacc[s];
#pragma unroll
        for (int off = 16; off; off >>= 1) v += __shfl_xor_sync(0xffffffffu, v, off);
        if (lane == 0) lred[wid * 4 + s] = v;
    }
    __syncthreads();
    if (tid < N_STAGES) {
        float sum = 0.f;
#pragma unroll
        for (int w = 0; w < 8; w++) sum += lred[w * 4 + tid];
        atomicAdd(&g_loss[tid], sum);
    }
}

__global__ void zero_loss_kernel() {
    if (threadIdx.x < N_STAGES) g_loss[threadIdx.x] = 0.f;
}

__global__ void finalize_loss_kernel(float* __restrict__ dout) {
    float total = g_loss[0] + g_loss[1] + g_loss[2] + g_loss[3];
    dout[OFF_LOSS] = (1.f + BETA) * total / (4.f * (float)BATCH * 64.f);
}

// ---------------- Launch ----------------
extern "C" void kernel_launch(void* const* d_in, const int* in_sizes, int n_in,
                              void* d_out, int out_size) {
    const float* x   = (const float*)d_in[0];
    const float* ew0 = (const float*)d_in[1];  const float* eb0 = (const float*)d_in[2];
    const float* ew1 = (const float*)d_in[3];  const float* eb1 = (const float*)d_in[4];
    const float* ew2 = (const float*)d_in[5];  const float* eb2 = (const float*)d_in[6];
    const float* ew3 = (const float*)d_in[7];  const float* eb3 = (const float*)d_in[8];
    const float* dw0 = (const float*)d_in[9];  const float* db0 = (const float*)d_in[10];
    const float* dw1 = (const float*)d_in[11]; const float* db1 = (const float*)d_in[12];
    const float* dw2 = (const float*)d_in[13]; const float* db2 = (const float*)d_in[14];
    const float* dw3 = (const float*)d_in[15]; const float* db3 = (const float*)d_in[16];
    const float* cb  = (const float*)d_in[17];
    float* out = (float*)d_out;

    float *bufA, *bufB, *bufC, *zb, *xqb;
    cudaGetSymbolAddress((void**)&bufA, g_bufA);
    cudaGetSymbolAddress((void**)&bufB, g_bufB);
    cudaGetSymbolAddress((void**)&bufC, g_bufC);
    cudaGetSymbolAddress((void**)&zb,   g_z);
    cudaGetSymbolAddress((void**)&xqb,  g_xq);

    cudaFuncSetAttribute(tf32_gemm<true >, cudaFuncAttributeMaxDynamicSharedMemorySize, TF32_SMEM);
    cudaFuncSetAttribute(tf32_gemm<false>, cudaFuncAttributeMaxDynamicSharedMemorySize, TF32_SMEM);
    cudaFuncSetAttribute(rq_kernel, cudaFuncAttributeMaxDynamicSharedMemorySize, RQ_SMEM);

    dim3 blk(256);
    const int MT = BATCH / 128;   // 512 M-tiles

    // Encoder: 768 -> 512 -> 256 -> 128 -> 64 (fp32 BK=8 scalar FFMA; R11-exact)
    gemm_kernel<128,128,8,8,8,true ><<<dim3(4, MT), blk>>>(x,    ew0, eb0, bufA, BATCH, 512, 768);
    gemm_kernel<128,128,8,8,8,true ><<<dim3(2, MT), blk>>>(bufA, ew1, eb1, bufB, BATCH, 256, 512);
    gemm_kernel<128,128,8,8,8,true ><<<dim3(1, MT), blk>>>(bufB, ew2, eb2, bufC, BATCH, 128, 256);
    gemm_kernel<128, 64,8,8,4,false><<<dim3(1, MT), blk>>>(bufC, ew3, eb3, zb,   BATCH,  64, 128);

    // Residual quantization (64 rows/block; indices -> d_out, x_q -> xqb)
    zero_loss_kernel<<<1, 32>>>();
    rq_kernel<<<BATCH / 64, 256, RQ_SMEM>>>(zb, cb, xqb, out);
    finalize_loss_kernel<<<1, 1>>>(out);

    // Decoder: tf32 mma.sync GEMMs (R11-proven, in-loop cvt).
    tf32_gemm<true ><<<dim3(1, MT), blk, TF32_SMEM>>>(xqb,  dw0, db0, bufC, 128,  64);
    tf32_gemm<true ><<<dim3(2, MT), blk, TF32_SMEM>>>(bufC, dw1, db1, bufB, 256, 128);
    tf32_gemm<true ><<<dim3(4, MT), blk, TF32_SMEM>>>(bufB, dw2, db2, bufA, 512, 256);
    tf32_gemm<false><<<dim3(6, MT), blk, TF32_SMEM>>>(bufA, dw3, db3, out,  768, 512);
}